// round 2
// baseline (speedup 1.0000x reference)
#include <cuda_runtime.h>
#include <cuda_bf16.h>
#include <cstddef>

// Problem constants
#define BB   2
#define LL   2048
#define DIMM 2048
#define HH   16
#define DD   128
#define E3   6144                 // 3*DIM
#define MROWS (BB*LL)             // 4096
#define BH   (BB*HH)              // 32

#define NEG_INF_F (__int_as_float(0xff800000))

// ---------------------------------------------------------------------------
// Scratch (device globals; allocation-free per harness rules)
// ---------------------------------------------------------------------------
__device__ float g_qkv[(size_t)MROWS * E3];       // [B*L, 3*DIM]   ~100 MB
__device__ float g_q  [(size_t)BH * LL * DD];     // [B,H,L,D]      ~33 MB
__device__ float g_k  [(size_t)BH * LL * DD];
__device__ float g_v  [(size_t)BH * LL * DD];
__device__ float g_s  [(size_t)BH * LL * LL];     // scores         ~536 MB
__device__ float g_o2 [(size_t)MROWS * DIMM];     // [B,L,H*D]      ~33 MB

// ---------------------------------------------------------------------------
// NT SGEMM: C[M,N] = alpha * A[M,K] @ B[N,K]^T (+ bias[n]), batched by z
// 128x128 tile, BK=8, 256 threads, 8x8 micro-tile per thread.
// All dims assumed multiples of tile sizes (true for every use here).
// ---------------------------------------------------------------------------
__global__ __launch_bounds__(256) void sgemm_nt(
    const float* __restrict__ A, const float* __restrict__ Bm,
    float* __restrict__ C, const float* __restrict__ bias,
    int K, int ldc, float alpha,
    long long sA, long long sB, long long sC)
{
    A  += (long long)blockIdx.z * sA;
    Bm += (long long)blockIdx.z * sB;
    C  += (long long)blockIdx.z * sC;

    __shared__ float As[8][128];
    __shared__ float Bs[8][128];

    const int tid  = threadIdx.x;
    const int m0   = blockIdx.y * 128;
    const int n0   = blockIdx.x * 128;
    const int arow = tid >> 1;          // 0..127
    const int acol = (tid & 1) * 4;     // 0 or 4
    const int tx   = tid & 15;
    const int ty   = tid >> 4;

    float acc[8][8];
#pragma unroll
    for (int i = 0; i < 8; i++)
#pragma unroll
        for (int j = 0; j < 8; j++) acc[i][j] = 0.f;

    const float* Aptr = A  + (long long)(m0 + arow) * K + acol;
    const float* Bptr = Bm + (long long)(n0 + arow) * K + acol;

    for (int k0 = 0; k0 < K; k0 += 8) {
        float4 av = *(const float4*)(Aptr + k0);
        float4 bv = *(const float4*)(Bptr + k0);
        __syncthreads();
        As[acol + 0][arow] = av.x; As[acol + 1][arow] = av.y;
        As[acol + 2][arow] = av.z; As[acol + 3][arow] = av.w;
        Bs[acol + 0][arow] = bv.x; Bs[acol + 1][arow] = bv.y;
        Bs[acol + 2][arow] = bv.z; Bs[acol + 3][arow] = bv.w;
        __syncthreads();
#pragma unroll
        for (int kk = 0; kk < 8; kk++) {
            float a[8], b[8];
            *(float4*)&a[0] = *(const float4*)&As[kk][ty * 8];
            *(float4*)&a[4] = *(const float4*)&As[kk][ty * 8 + 4];
            *(float4*)&b[0] = *(const float4*)&Bs[kk][tx * 8];
            *(float4*)&b[4] = *(const float4*)&Bs[kk][tx * 8 + 4];
#pragma unroll
            for (int i = 0; i < 8; i++)
#pragma unroll
                for (int j = 0; j < 8; j++)
                    acc[i][j] = fmaf(a[i], b[j], acc[i][j]);
        }
    }

#pragma unroll
    for (int i = 0; i < 8; i++) {
        long long row = (long long)(m0 + ty * 8 + i) * ldc + n0 + tx * 8;
#pragma unroll
        for (int j = 0; j < 8; j += 4) {
            float4 o;
            o.x = acc[i][j + 0] * alpha;
            o.y = acc[i][j + 1] * alpha;
            o.z = acc[i][j + 2] * alpha;
            o.w = acc[i][j + 3] * alpha;
            if (bias) {
                o.x += bias[n0 + tx * 8 + j + 0];
                o.y += bias[n0 + tx * 8 + j + 1];
                o.z += bias[n0 + tx * 8 + j + 2];
                o.w += bias[n0 + tx * 8 + j + 3];
            }
            *(float4*)(C + row + j) = o;
        }
    }
}

// ---------------------------------------------------------------------------
// PV GEMM (NN): per (b,h): O[l, d] = sum_k P[l,k] * V[k,d]
// M=L, N=D=128, K=L. Writes directly into [B, L, H*D] layout (folds transpose).
// ---------------------------------------------------------------------------
__global__ __launch_bounds__(256) void pv_gemm(
    const float* __restrict__ S, const float* __restrict__ V, float* __restrict__ O)
{
    const int bz = blockIdx.z;
    const int b = bz >> 4, h = bz & 15;
    const float* A  = S + (long long)bz * LL * LL;     // [L, L]
    const float* Bv = V + (long long)bz * LL * DD;     // [L, D]
    float* C = O + (long long)b * LL * DIMM + h * DD;  // row stride DIMM

    __shared__ float As[8][128];
    __shared__ float Bs[8][128];

    const int tid  = threadIdx.x;
    const int m0   = blockIdx.y * 128;
    const int arow = tid >> 1;
    const int acol = (tid & 1) * 4;
    const int bkk  = tid >> 5;          // 0..7
    const int bn4  = (tid & 31) * 4;    // 0..124
    const int tx   = tid & 15;
    const int ty   = tid >> 4;

    float acc[8][8];
#pragma unroll
    for (int i = 0; i < 8; i++)
#pragma unroll
        for (int j = 0; j < 8; j++) acc[i][j] = 0.f;

    const float* Aptr = A + (long long)(m0 + arow) * LL + acol;

    for (int k0 = 0; k0 < LL; k0 += 8) {
        float4 av = *(const float4*)(Aptr + k0);
        float4 bv = *(const float4*)(Bv + (long long)(k0 + bkk) * DD + bn4);
        __syncthreads();
        As[acol + 0][arow] = av.x; As[acol + 1][arow] = av.y;
        As[acol + 2][arow] = av.z; As[acol + 3][arow] = av.w;
        *(float4*)&Bs[bkk][bn4] = bv;
        __syncthreads();
#pragma unroll
        for (int kk = 0; kk < 8; kk++) {
            float a[8], bb[8];
            *(float4*)&a[0]  = *(const float4*)&As[kk][ty * 8];
            *(float4*)&a[4]  = *(const float4*)&As[kk][ty * 8 + 4];
            *(float4*)&bb[0] = *(const float4*)&Bs[kk][tx * 8];
            *(float4*)&bb[4] = *(const float4*)&Bs[kk][tx * 8 + 4];
#pragma unroll
            for (int i = 0; i < 8; i++)
#pragma unroll
                for (int j = 0; j < 8; j++)
                    acc[i][j] = fmaf(a[i], bb[j], acc[i][j]);
        }
    }

#pragma unroll
    for (int i = 0; i < 8; i++) {
        long long row = (long long)(m0 + ty * 8 + i) * DIMM + tx * 8;
#pragma unroll
        for (int j = 0; j < 8; j += 4) {
            float4 o;
            o.x = acc[i][j + 0]; o.y = acc[i][j + 1];
            o.z = acc[i][j + 2]; o.w = acc[i][j + 3];
            *(float4*)(C + row + j) = o;
        }
    }
}

// ---------------------------------------------------------------------------
// Prep: split qkv -> q,k,v in [B,H,L,D]; RMSNorm(q,k) with scale; RoPE(q,k).
// One warp per (b,h,l) row. D=128 -> 4 floats per lane.
// ---------------------------------------------------------------------------
__global__ __launch_bounds__(256) void prep_kernel(
    const float* __restrict__ qkv, const float* __restrict__ pe,
    const float* __restrict__ qsc, const float* __restrict__ ksc,
    float* __restrict__ q, float* __restrict__ k, float* __restrict__ v)
{
    const int warp = (blockIdx.x * blockDim.x + threadIdx.x) >> 5;  // 0..BH*LL-1
    const int lane = threadIdx.x & 31;
    const int b = warp >> 15;            // / (H*L) = /32768
    const int rem = warp & 32767;
    const int h = rem >> 11;             // / L
    const int l = rem & 2047;

    const long long src = ((long long)(b * LL + l)) * E3 + h * DD + lane * 4;
    float4 qv = *(const float4*)(qkv + src);
    float4 kv = *(const float4*)(qkv + src + DIMM);
    float4 vv = *(const float4*)(qkv + src + 2 * DIMM);

    // RMS norm q
    float sq = qv.x * qv.x + qv.y * qv.y + qv.z * qv.z + qv.w * qv.w;
#pragma unroll
    for (int o = 16; o; o >>= 1) sq += __shfl_xor_sync(0xffffffffu, sq, o);
    float rq = rsqrtf(sq * (1.0f / 128.0f) + 1e-6f);
    float4 qs4 = *(const float4*)(qsc + lane * 4);
    qv.x *= rq * qs4.x; qv.y *= rq * qs4.y; qv.z *= rq * qs4.z; qv.w *= rq * qs4.w;

    // RMS norm k
    float sk = kv.x * kv.x + kv.y * kv.y + kv.z * kv.z + kv.w * kv.w;
#pragma unroll
    for (int o = 16; o; o >>= 1) sk += __shfl_xor_sync(0xffffffffu, sk, o);
    float rk = rsqrtf(sk * (1.0f / 128.0f) + 1e-6f);
    float4 ks4 = *(const float4*)(ksc + lane * 4);
    kv.x *= rk * ks4.x; kv.y *= rk * ks4.y; kv.z *= rk * ks4.z; kv.w *= rk * ks4.w;

    // RoPE: lane holds d = 4*lane..4*lane+3 -> pairs j0=2*lane, j1=2*lane+1
    // pe flat: [l, j, r, c] -> l*256 + j*4 + r*2 + c
    const float* peb = pe + (long long)l * 256 + lane * 8;
    float a00 = peb[0], a01 = peb[1], a10 = peb[2], a11 = peb[3];
    float b00 = peb[4], b01 = peb[5], b10 = peb[6], b11 = peb[7];

    float4 qo, ko;
    qo.x = a00 * qv.x + a01 * qv.y;  qo.y = a10 * qv.x + a11 * qv.y;
    qo.z = b00 * qv.z + b01 * qv.w;  qo.w = b10 * qv.z + b11 * qv.w;
    ko.x = a00 * kv.x + a01 * kv.y;  ko.y = a10 * kv.x + a11 * kv.y;
    ko.z = b00 * kv.z + b01 * kv.w;  ko.w = b10 * kv.z + b11 * kv.w;

    const long long dst = (long long)warp * DD + lane * 4;  // [B,H,L,D]
    *(float4*)(q + dst) = qo;
    *(float4*)(k + dst) = ko;
    *(float4*)(v + dst) = vv;
}

// ---------------------------------------------------------------------------
// Row softmax over last dim (L=2048), one block (256 threads) per row.
// ---------------------------------------------------------------------------
__global__ __launch_bounds__(256) void softmax_rows(float* __restrict__ s)
{
    float* p = s + (long long)blockIdx.x * LL;
    const int tid = threadIdx.x;
    const int lane = tid & 31, wid = tid >> 5;
    __shared__ float red[8];

    float vals[8];
    float m = NEG_INF_F;
#pragma unroll
    for (int i = 0; i < 8; i++) {
        vals[i] = p[tid + i * 256];
        m = fmaxf(m, vals[i]);
    }
#pragma unroll
    for (int o = 16; o; o >>= 1) m = fmaxf(m, __shfl_xor_sync(0xffffffffu, m, o));
    if (lane == 0) red[wid] = m;
    __syncthreads();
    float mm = red[0];
#pragma unroll
    for (int i = 1; i < 8; i++) mm = fmaxf(mm, red[i]);
    __syncthreads();

    float sum = 0.f;
#pragma unroll
    for (int i = 0; i < 8; i++) {
        vals[i] = __expf(vals[i] - mm);
        sum += vals[i];
    }
#pragma unroll
    for (int o = 16; o; o >>= 1) sum += __shfl_xor_sync(0xffffffffu, sum, o);
    if (lane == 0) red[wid] = sum;
    __syncthreads();
    float total = 0.f;
#pragma unroll
    for (int i = 0; i < 8; i++) total += red[i];
    float inv = 1.0f / total;
#pragma unroll
    for (int i = 0; i < 8; i++) p[tid + i * 256] = vals[i] * inv;
}

// ---------------------------------------------------------------------------
// Launch
// ---------------------------------------------------------------------------
extern "C" void kernel_launch(void* const* d_in, const int* in_sizes, int n_in,
                              void* d_out, int out_size)
{
    const float* x      = (const float*)d_in[0];  // [B,L,DIM]
    const float* pe     = (const float*)d_in[1];  // [1,1,L,D/2,2,2]
    const float* qkv_w  = (const float*)d_in[2];  // [3*DIM, DIM]
    const float* q_sc   = (const float*)d_in[3];  // [D]
    const float* k_sc   = (const float*)d_in[4];  // [D]
    const float* proj_w = (const float*)d_in[5];  // [DIM, DIM]
    const float* proj_b = (const float*)d_in[6];  // [DIM]
    float* out = (float*)d_out;                   // [B,L,DIM]

    float *qkv, *q, *k, *v, *s, *o2;
    cudaGetSymbolAddress((void**)&qkv, g_qkv);
    cudaGetSymbolAddress((void**)&q,   g_q);
    cudaGetSymbolAddress((void**)&k,   g_k);
    cudaGetSymbolAddress((void**)&v,   g_v);
    cudaGetSymbolAddress((void**)&s,   g_s);
    cudaGetSymbolAddress((void**)&o2,  g_o2);

    const float attn_scale = 0.08838834764831845f;  // 1/sqrt(128)

    // 1) QKV projection: [4096,2048] @ [6144,2048]^T -> [4096,6144]
    sgemm_nt<<<dim3(E3 / 128, MROWS / 128, 1), 256>>>(
        x, qkv_w, qkv, nullptr, DIMM, E3, 1.0f, 0, 0, 0);

    // 2) Split + RMSNorm + RoPE -> q,k,v in [B,H,L,D]
    prep_kernel<<<(BH * LL) / 8, 256>>>(qkv, pe, q_sc, k_sc, q, k, v);

    // 3) Scores: per (b,h): Q[L,D] @ K[L,D]^T * scale -> [L,L]
    sgemm_nt<<<dim3(LL / 128, LL / 128, BH), 256>>>(
        q, k, s, nullptr, DD, LL, attn_scale,
        (long long)LL * DD, (long long)LL * DD, (long long)LL * LL);

    // 4) Softmax over keys
    softmax_rows<<<BH * LL, 256>>>(s);

    // 5) P @ V -> o2 in [B,L,H*D] layout
    pv_gemm<<<dim3(1, LL / 128, BH), 256>>>(s, v, o2);

    // 6) Output projection + bias: [4096,2048] @ [2048,2048]^T + b
    sgemm_nt<<<dim3(DIMM / 128, MROWS / 128, 1), 256>>>(
        o2, proj_w, out, proj_b, DIMM, DIMM, 1.0f, 0, 0, 0);
}

// round 4
// speedup vs baseline: 1.6452x; 1.6452x over previous
#include <cuda_runtime.h>
#include <cuda_bf16.h>
#include <cstdint>
#include <cstddef>

// Problem constants
#define BB   2
#define LL   2048
#define DIMM 2048
#define HH   16
#define DD   128
#define E3   6144
#define MROWS (BB*LL)
#define BH   (BB*HH)

#define NEG_INF_F (__int_as_float(0xff800000))

// GEMM tiling
#define BM 128
#define BN 128
#define BK 32
#define SKP 40                      // padded k-stride in elements (80 B, conflict-free)
#define STAGE_ELEMS (128 * SKP)     // per matrix per stage (bf16 elements)
#define STAGE_BYTES (STAGE_ELEMS * 2)
#define SMEM_STAGE (4 * STAGE_BYTES)       // A_hi, A_lo, B_hi, B_lo
#define SMEM_TOTAL (2 * SMEM_STAGE)        // double buffered = 81920 B

// ---------------------------------------------------------------------------
// Scratch
// ---------------------------------------------------------------------------
__device__ float g_qkv[(size_t)MROWS * E3];
__device__ float g_q  [(size_t)BH * LL * DD];
__device__ float g_k  [(size_t)BH * LL * DD];
__device__ float g_v  [(size_t)BH * LL * DD];
__device__ float g_s  [(size_t)BH * LL * LL];
__device__ float g_o2 [(size_t)MROWS * DIMM];

// ---------------------------------------------------------------------------
// mma.sync bf16 (m16n8k16), fp32 accumulate
// ---------------------------------------------------------------------------
__device__ __forceinline__ void mma_bf16(float* d, const uint32_t* a, const uint32_t* b) {
    asm volatile(
        "mma.sync.aligned.m16n8k16.row.col.f32.bf16.bf16.f32 "
        "{%0,%1,%2,%3}, {%4,%5,%6,%7}, {%8,%9}, {%0,%1,%2,%3};"
        : "+f"(d[0]), "+f"(d[1]), "+f"(d[2]), "+f"(d[3])
        : "r"(a[0]), "r"(a[1]), "r"(a[2]), "r"(a[3]), "r"(b[0]), "r"(b[1]));
}

__device__ __forceinline__ void split_hi_lo(float x, __nv_bfloat16& h, __nv_bfloat16& l) {
    h = __float2bfloat16_rn(x);
    l = __float2bfloat16_rn(x - __bfloat162float(h));
}

// ---------------------------------------------------------------------------
// Tensor-core GEMM (hi/lo split): C[M,N] = alpha * A[M,K] @ op(B)^T (+ bias)
//   transB=0: B is [N,K] row-major.  transB=1: B is [K,N] row-major.
// ---------------------------------------------------------------------------
__global__ __launch_bounds__(256) void gemm_tc(
    const float* __restrict__ A, const float* __restrict__ B,
    float* __restrict__ C, const float* __restrict__ bias,
    int K, int lda, int ldb, int ldc, float alpha,
    long long sA, long long sB, long long sC,
    int transB, int pvC)
{
    extern __shared__ __nv_bfloat16 sm[];
    const int tid  = threadIdx.x;
    const int lane = tid & 31;
    const int wrp  = tid >> 5;
    const int wy   = wrp >> 2;     // 0..1 (m)
    const int wx   = wrp & 3;      // 0..3 (n)
    const int bz   = blockIdx.z;

    A += (long long)bz * sA;
    B += (long long)bz * sB;
    if (pvC) C += (long long)(bz >> 4) * LL * DIMM + (long long)(bz & 15) * DD;
    else     C += (long long)bz * sC;

    const int m0 = blockIdx.y * BM;
    const int n0 = blockIdx.x * BN;

    float acc[4][4][4];
#pragma unroll
    for (int m = 0; m < 4; m++)
#pragma unroll
        for (int n = 0; n < 4; n++)
#pragma unroll
            for (int i = 0; i < 4; i++) acc[m][n][i] = 0.f;

    const int nchunks = K >> 5;

    // A staging indices: 128 rows x 32 k; each thread: one row-half (16 k)
    const int ar = tid >> 1;
    const int ak = (tid & 1) * 16;
    // B staging (transB=1): 32 k-rows x 128 n; thread: kk row, 16 n
    const int bkk = tid >> 3;
    const int bnb = (tid & 7) * 16;

    float4 aP[4], bP[4];

    // prefetch chunk 0
    {
        const float* ap = A + (long long)(m0 + ar) * lda + ak;
#pragma unroll
        for (int i = 0; i < 4; i++) aP[i] = *(const float4*)(ap + i * 4);
        if (!transB) {
            const float* bp = B + (long long)(n0 + ar) * ldb + ak;
#pragma unroll
            for (int i = 0; i < 4; i++) bP[i] = *(const float4*)(bp + i * 4);
        } else {
            const float* bp = B + (long long)bkk * ldb + n0 + bnb;
#pragma unroll
            for (int i = 0; i < 4; i++) bP[i] = *(const float4*)(bp + i * 4);
        }
    }

    for (int c = 0; c < nchunks; c++) {
        const int s = c & 1;
        __nv_bfloat16* Ah = sm + s * (SMEM_STAGE / 2);
        __nv_bfloat16* Al = Ah + STAGE_ELEMS;
        __nv_bfloat16* Bh = Al + STAGE_ELEMS;
        __nv_bfloat16* Bl = Bh + STAGE_ELEMS;

        // ---- convert + store staged regs into smem ----
        {
            const int off = ar * SKP + ak;
#pragma unroll
            for (int i = 0; i < 4; i++) {
                const float f[4] = { aP[i].x, aP[i].y, aP[i].z, aP[i].w };
                __nv_bfloat16 h[4], l[4];
#pragma unroll
                for (int j = 0; j < 4; j++) split_hi_lo(f[j], h[j], l[j]);
                *(uint2*)(Ah + off + i * 4) = *(uint2*)h;
                *(uint2*)(Al + off + i * 4) = *(uint2*)l;
            }
        }
        if (!transB) {
            const int off = ar * SKP + ak;
#pragma unroll
            for (int i = 0; i < 4; i++) {
                const float f[4] = { bP[i].x, bP[i].y, bP[i].z, bP[i].w };
                __nv_bfloat16 h[4], l[4];
#pragma unroll
                for (int j = 0; j < 4; j++) split_hi_lo(f[j], h[j], l[j]);
                *(uint2*)(Bh + off + i * 4) = *(uint2*)h;
                *(uint2*)(Bl + off + i * 4) = *(uint2*)l;
            }
        } else {
#pragma unroll
            for (int i = 0; i < 4; i++) {
                const float f[4] = { bP[i].x, bP[i].y, bP[i].z, bP[i].w };
#pragma unroll
                for (int j = 0; j < 4; j++) {
                    const int n = bnb + i * 4 + j;
                    __nv_bfloat16 h, l;
                    split_hi_lo(f[j], h, l);
                    Bh[n * SKP + bkk] = h;
                    Bl[n * SKP + bkk] = l;
                }
            }
        }

        __syncthreads();

        // ---- prefetch next chunk ----
        if (c + 1 < nchunks) {
            const int k0 = (c + 1) << 5;
            const float* ap = A + (long long)(m0 + ar) * lda + k0 + ak;
#pragma unroll
            for (int i = 0; i < 4; i++) aP[i] = *(const float4*)(ap + i * 4);
            if (!transB) {
                const float* bp = B + (long long)(n0 + ar) * ldb + k0 + ak;
#pragma unroll
                for (int i = 0; i < 4; i++) bP[i] = *(const float4*)(bp + i * 4);
            } else {
                const float* bp = B + (long long)(k0 + bkk) * ldb + n0 + bnb;
#pragma unroll
                for (int i = 0; i < 4; i++) bP[i] = *(const float4*)(bp + i * 4);
            }
        }

        // ---- compute: 2 k-steps of 16 ----
#pragma unroll
        for (int ks = 0; ks < 2; ks++) {
            uint32_t aH[4][4], aL[4][4];
#pragma unroll
            for (int m = 0; m < 4; m++) {
                const int rbase = wy * 64 + m * 16 + (lane >> 2);
                const int kbase = ks * 16 + (lane & 3) * 2;
#pragma unroll
                for (int j = 0; j < 4; j++) {
                    const int off = (rbase + (j & 1) * 8) * SKP + kbase + (j >> 1) * 8;
                    aH[m][j] = *(const uint32_t*)(Ah + off);
                    aL[m][j] = *(const uint32_t*)(Al + off);
                }
            }
            uint32_t bH[4][2], bL[4][2];
#pragma unroll
            for (int n = 0; n < 4; n++) {
                const int off = (wx * 32 + n * 8 + (lane >> 2)) * SKP
                              + ks * 16 + (lane & 3) * 2;
                bH[n][0] = *(const uint32_t*)(Bh + off);
                bH[n][1] = *(const uint32_t*)(Bh + off + 8);
                bL[n][0] = *(const uint32_t*)(Bl + off);
                bL[n][1] = *(const uint32_t*)(Bl + off + 8);
            }
#pragma unroll
            for (int m = 0; m < 4; m++)
#pragma unroll
                for (int n = 0; n < 4; n++) {
                    mma_bf16(acc[m][n], aH[m], bH[n]);
                    mma_bf16(acc[m][n], aH[m], bL[n]);
                    mma_bf16(acc[m][n], aL[m], bH[n]);
                }
        }
    }

    // ---- epilogue ----
#pragma unroll
    for (int m = 0; m < 4; m++) {
        const int row = m0 + wy * 64 + m * 16 + (lane >> 2);
#pragma unroll
        for (int n = 0; n < 4; n++) {
            const int col = n0 + wx * 32 + n * 8 + (lane & 3) * 2;
            float2 v0, v1;
            v0.x = acc[m][n][0] * alpha; v0.y = acc[m][n][1] * alpha;
            v1.x = acc[m][n][2] * alpha; v1.y = acc[m][n][3] * alpha;
            if (bias) {
                float2 bb = *(const float2*)(bias + col);
                v0.x += bb.x; v0.y += bb.y;
                v1.x += bb.x; v1.y += bb.y;
            }
            *(float2*)(C + (long long)row * ldc + col)       = v0;
            *(float2*)(C + (long long)(row + 8) * ldc + col) = v1;
        }
    }
}

// ---------------------------------------------------------------------------
// Prep: split qkv -> q,k,v in [B,H,L,D]; RMSNorm(q,k); RoPE(q,k).
// ---------------------------------------------------------------------------
__global__ __launch_bounds__(256) void prep_kernel(
    const float* __restrict__ qkv, const float* __restrict__ pe,
    const float* __restrict__ qsc, const float* __restrict__ ksc,
    float* __restrict__ q, float* __restrict__ k, float* __restrict__ v)
{
    const int warp = (blockIdx.x * blockDim.x + threadIdx.x) >> 5;
    const int lane = threadIdx.x & 31;
    const int b = warp >> 15;
    const int rem = warp & 32767;
    const int h = rem >> 11;
    const int l = rem & 2047;

    const long long src = ((long long)(b * LL + l)) * E3 + h * DD + lane * 4;
    float4 qv = *(const float4*)(qkv + src);
    float4 kv = *(const float4*)(qkv + src + DIMM);
    float4 vv = *(const float4*)(qkv + src + 2 * DIMM);

    float sq = qv.x * qv.x + qv.y * qv.y + qv.z * qv.z + qv.w * qv.w;
#pragma unroll
    for (int o = 16; o; o >>= 1) sq += __shfl_xor_sync(0xffffffffu, sq, o);
    float rq = rsqrtf(sq * (1.0f / 128.0f) + 1e-6f);
    float4 qs4 = *(const float4*)(qsc + lane * 4);
    qv.x *= rq * qs4.x; qv.y *= rq * qs4.y; qv.z *= rq * qs4.z; qv.w *= rq * qs4.w;

    float sk = kv.x * kv.x + kv.y * kv.y + kv.z * kv.z + kv.w * kv.w;
#pragma unroll
    for (int o = 16; o; o >>= 1) sk += __shfl_xor_sync(0xffffffffu, sk, o);
    float rk = rsqrtf(sk * (1.0f / 128.0f) + 1e-6f);
    float4 ks4 = *(const float4*)(ksc + lane * 4);
    kv.x *= rk * ks4.x; kv.y *= rk * ks4.y; kv.z *= rk * ks4.z; kv.w *= rk * ks4.w;

    const float* peb = pe + (long long)l * 256 + lane * 8;
    float a00 = peb[0], a01 = peb[1], a10 = peb[2], a11 = peb[3];
    float b00 = peb[4], b01 = peb[5], b10 = peb[6], b11 = peb[7];

    float4 qo, ko;
    qo.x = a00 * qv.x + a01 * qv.y;  qo.y = a10 * qv.x + a11 * qv.y;
    qo.z = b00 * qv.z + b01 * qv.w;  qo.w = b10 * qv.z + b11 * qv.w;
    ko.x = a00 * kv.x + a01 * kv.y;  ko.y = a10 * kv.x + a11 * kv.y;
    ko.z = b00 * kv.z + b01 * kv.w;  ko.w = b10 * kv.z + b11 * kv.w;

    const long long dst = (long long)warp * DD + lane * 4;
    *(float4*)(q + dst) = qo;
    *(float4*)(k + dst) = ko;
    *(float4*)(v + dst) = vv;
}

// ---------------------------------------------------------------------------
// Row softmax over last dim (L=2048).
// ---------------------------------------------------------------------------
__global__ __launch_bounds__(256) void softmax_rows(float* __restrict__ s)
{
    float* p = s + (long long)blockIdx.x * LL;
    const int tid = threadIdx.x;
    const int lane = tid & 31, wid = tid >> 5;
    __shared__ float red[8];

    float vals[8];
    float m = NEG_INF_F;
#pragma unroll
    for (int i = 0; i < 8; i++) {
        vals[i] = p[tid + i * 256];
        m = fmaxf(m, vals[i]);
    }
#pragma unroll
    for (int o = 16; o; o >>= 1) m = fmaxf(m, __shfl_xor_sync(0xffffffffu, m, o));
    if (lane == 0) red[wid] = m;
    __syncthreads();
    float mm = red[0];
#pragma unroll
    for (int i = 1; i < 8; i++) mm = fmaxf(mm, red[i]);
    __syncthreads();

    float sum = 0.f;
#pragma unroll
    for (int i = 0; i < 8; i++) {
        vals[i] = __expf(vals[i] - mm);
        sum += vals[i];
    }
#pragma unroll
    for (int o = 16; o; o >>= 1) sum += __shfl_xor_sync(0xffffffffu, sum, o);
    if (lane == 0) red[wid] = sum;
    __syncthreads();
    float total = 0.f;
#pragma unroll
    for (int i = 0; i < 8; i++) total += red[i];
    float inv = 1.0f / total;
#pragma unroll
    for (int i = 0; i < 8; i++) p[tid + i * 256] = vals[i] * inv;
}

// ---------------------------------------------------------------------------
// Launch
// ---------------------------------------------------------------------------
extern "C" void kernel_launch(void* const* d_in, const int* in_sizes, int n_in,
                              void* d_out, int out_size)
{
    const float* x      = (const float*)d_in[0];
    const float* pe     = (const float*)d_in[1];
    const float* qkv_w  = (const float*)d_in[2];
    const float* q_sc   = (const float*)d_in[3];
    const float* k_sc   = (const float*)d_in[4];
    const float* proj_w = (const float*)d_in[5];
    const float* proj_b = (const float*)d_in[6];
    float* out = (float*)d_out;

    float *qkv, *q, *k, *v, *s, *o2;
    cudaGetSymbolAddress((void**)&qkv, g_qkv);
    cudaGetSymbolAddress((void**)&q,   g_q);
    cudaGetSymbolAddress((void**)&k,   g_k);
    cudaGetSymbolAddress((void**)&v,   g_v);
    cudaGetSymbolAddress((void**)&s,   g_s);
    cudaGetSymbolAddress((void**)&o2,  g_o2);

    cudaFuncSetAttribute(gemm_tc, cudaFuncAttributeMaxDynamicSharedMemorySize, SMEM_TOTAL);

    const float attn_scale = 0.08838834764831845f;  // 1/sqrt(128)

    // 1) QKV: [4096,2048] @ [6144,2048]^T -> [4096,6144]
    gemm_tc<<<dim3(E3 / BN, MROWS / BM, 1), 256, SMEM_TOTAL>>>(
        x, qkv_w, qkv, nullptr, DIMM, DIMM, DIMM, E3, 1.0f, 0, 0, 0, 0, 0);

    // 2) Split + RMSNorm + RoPE
    prep_kernel<<<(BH * LL) / 8, 256>>>(qkv, pe, q_sc, k_sc, q, k, v);

    // 3) Scores: per (b,h): Q[L,D] @ K[L,D]^T * scale
    gemm_tc<<<dim3(LL / BN, LL / BM, BH), 256, SMEM_TOTAL>>>(
        q, k, s, nullptr, DD, DD, DD, LL, attn_scale,
        (long long)LL * DD, (long long)LL * DD, (long long)LL * LL, 0, 0);

    // 4) Softmax
    softmax_rows<<<BH * LL, 256>>>(s);

    // 5) P @ V -> o2 [B,L,H*D]  (V is [K=L, N=D] -> transB)
    gemm_tc<<<dim3(1, LL / BM, BH), 256, SMEM_TOTAL>>>(
        s, v, o2, nullptr, LL, LL, DD, DIMM, 1.0f,
        (long long)LL * LL, (long long)LL * DD, 0, 1, 1);

    // 6) Proj + bias
    gemm_tc<<<dim3(DIMM / BN, MROWS / BM, 1), 256, SMEM_TOTAL>>>(
        o2, proj_w, out, proj_b, DIMM, DIMM, DIMM, DIMM, 1.0f, 0, 0, 0, 0, 0);
}

// round 5
// speedup vs baseline: 2.1910x; 1.3317x over previous
#include <cuda_runtime.h>
#include <cuda_bf16.h>
#include <cstdint>
#include <cstddef>

#define BB   2
#define LL   2048
#define DIMM 2048
#define HH   16
#define DD   128
#define E3   6144
#define MROWS (BB*LL)
#define BH   (BB*HH)

#define NEG_INF_F (__int_as_float(0xff800000))

// GEMM tiling
#define BM 128
#define BN 128
#define BK 32
#define SKP 40                          // padded k-stride (80 B rows)
#define STG_E (128 * SKP)               // elems per array per stage
#define STG_B (STG_E * 2)               // 10240 B
#define SMEM_STAGE (4 * STG_B)          // Ah, Al, Bh, Bl
#define SMEM_TOTAL (2 * SMEM_STAGE)     // 81920 B

// ---------------------------------------------------------------------------
// Scratch
// ---------------------------------------------------------------------------
__device__ float g_qkv[(size_t)MROWS * E3];
__device__ float g_s  [(size_t)BH * LL * LL];

__device__ __nv_bfloat16 g_xh[(size_t)MROWS * DIMM], g_xl[(size_t)MROWS * DIMM];
__device__ __nv_bfloat16 g_wqh[(size_t)E3 * DIMM],  g_wql[(size_t)E3 * DIMM];
__device__ __nv_bfloat16 g_wph[(size_t)DIMM * DIMM], g_wpl[(size_t)DIMM * DIMM];
__device__ __nv_bfloat16 g_qh[(size_t)BH * LL * DD], g_ql[(size_t)BH * LL * DD];
__device__ __nv_bfloat16 g_kh[(size_t)BH * LL * DD], g_kl[(size_t)BH * LL * DD];
__device__ __nv_bfloat16 g_vh[(size_t)BH * LL * DD], g_vl[(size_t)BH * LL * DD];
__device__ __nv_bfloat16 g_sh[(size_t)BH * LL * LL], g_sl[(size_t)BH * LL * LL];
__device__ __nv_bfloat16 g_oh[(size_t)MROWS * DIMM], g_ol[(size_t)MROWS * DIMM];

// ---------------------------------------------------------------------------
// PTX helpers
// ---------------------------------------------------------------------------
__device__ __forceinline__ uint32_t smem_u32(const void* p) {
    uint32_t a;
    asm("{ .reg .u64 t; cvta.to.shared.u64 t, %1; cvt.u32.u64 %0, t; }" : "=r"(a) : "l"(p));
    return a;
}

#define CP16(dst, src) \
    asm volatile("cp.async.cg.shared.global [%0], [%1], 16;" :: "r"(dst), "l"(src))
#define CP_COMMIT() asm volatile("cp.async.commit_group;" ::: "memory")
#define CP_WAIT(n)  asm volatile("cp.async.wait_group %0;" :: "n"(n) : "memory")

#define LDSM_X4(r, addr) \
    asm volatile("ldmatrix.sync.aligned.m8n8.x4.shared.b16 {%0,%1,%2,%3}, [%4];" \
        : "=r"((r)[0]), "=r"((r)[1]), "=r"((r)[2]), "=r"((r)[3]) : "r"(addr))
#define LDSM_X2(r, addr) \
    asm volatile("ldmatrix.sync.aligned.m8n8.x2.shared.b16 {%0,%1}, [%2];" \
        : "=r"((r)[0]), "=r"((r)[1]) : "r"(addr))

__device__ __forceinline__ void mma_bf16(float* d, const uint32_t* a, const uint32_t* b) {
    asm volatile(
        "mma.sync.aligned.m16n8k16.row.col.f32.bf16.bf16.f32 "
        "{%0,%1,%2,%3}, {%4,%5,%6,%7}, {%8,%9}, {%0,%1,%2,%3};"
        : "+f"(d[0]), "+f"(d[1]), "+f"(d[2]), "+f"(d[3])
        : "r"(a[0]), "r"(a[1]), "r"(a[2]), "r"(a[3]), "r"(b[0]), "r"(b[1]));
}

__device__ __forceinline__ void split2(float x, float y,
                                       uint32_t& hi, uint32_t& lo) {
    __nv_bfloat162 h = __floats2bfloat162_rn(x, y);
    __nv_bfloat162 l = __floats2bfloat162_rn(x - __bfloat162float(h.x),
                                             y - __bfloat162float(h.y));
    hi = *(uint32_t*)&h;
    lo = *(uint32_t*)&l;
}

// ---------------------------------------------------------------------------
// Elementwise fp32 -> bf16 hi/lo converter
// ---------------------------------------------------------------------------
__global__ __launch_bounds__(256) void convert_hl(
    const float* __restrict__ src, __nv_bfloat16* __restrict__ h,
    __nv_bfloat16* __restrict__ l, int n4)
{
    int i = blockIdx.x * blockDim.x + threadIdx.x;
    if (i >= n4) return;
    float4 f = *(const float4*)(src + i * 4);
    uint2 hv, lv;
    split2(f.x, f.y, hv.x, lv.x);
    split2(f.z, f.w, hv.y, lv.y);
    *(uint2*)(h + i * 4) = hv;
    *(uint2*)(l + i * 4) = lv;
}

// ---------------------------------------------------------------------------
// Tensor-core GEMM on pre-split bf16 hi/lo inputs.
//   C = alpha * A @ op(B)^T (+bias).  transB=0: B=[N,K]; transB=1: B=[K,N].
//   outHL: write bf16 hi/lo into g_oh/g_ol at PV layout instead of fp32 C.
// ---------------------------------------------------------------------------
__global__ __launch_bounds__(256) void gemm_tc(
    const __nv_bfloat16* __restrict__ Ahg, const __nv_bfloat16* __restrict__ Alg,
    const __nv_bfloat16* __restrict__ Bhg, const __nv_bfloat16* __restrict__ Blg,
    float* __restrict__ C, const float* __restrict__ bias,
    int K, int lda, int ldb, int ldc, float alpha,
    long long sA, long long sB, long long sC,
    int transB, int outHL)
{
    extern __shared__ __nv_bfloat16 sm[];
    const uint32_t smb = smem_u32(sm);
    const int tid  = threadIdx.x;
    const int lane = tid & 31;
    const int wrp  = tid >> 5;
    const int wy   = wrp >> 2;
    const int wx   = wrp & 3;
    const int bz   = blockIdx.z;

    Ahg += (long long)bz * sA;  Alg += (long long)bz * sA;
    Bhg += (long long)bz * sB;  Blg += (long long)bz * sB;
    long long cOff;
    if (outHL) cOff = (long long)(bz >> 4) * LL * DIMM + (long long)(bz & 15) * DD;
    else       cOff = (long long)bz * sC;

    const int m0 = blockIdx.y * BM;
    const int n0 = blockIdx.x * BN;

    float acc[4][4][4];
#pragma unroll
    for (int m = 0; m < 4; m++)
#pragma unroll
        for (int n = 0; n < 4; n++)
#pragma unroll
            for (int i = 0; i < 4; i++) acc[m][n][i] = 0.f;

    const int nchunks = K >> 5;

    // staging indices
    const int ar = tid >> 1;
    const int ak = (tid & 1) * 16;
    const int bkk = tid >> 3;          // transB
    const int bnb = (tid & 7) * 16;

    auto issue = [&](int c) {
        const int s = c & 1;
        const int k0 = c << 5;
        const uint32_t sb = smb + s * SMEM_STAGE;
        const uint32_t aoff = (uint32_t)(ar * SKP + ak) * 2u;
        // A hi/lo
        CP16(sb + aoff,              Ahg + (long long)(m0 + ar) * lda + k0 + ak);
        CP16(sb + aoff + 16,         Ahg + (long long)(m0 + ar) * lda + k0 + ak + 8);
        CP16(sb + STG_B + aoff,      Alg + (long long)(m0 + ar) * lda + k0 + ak);
        CP16(sb + STG_B + aoff + 16, Alg + (long long)(m0 + ar) * lda + k0 + ak + 8);
        if (!transB) {
            CP16(sb + 2 * STG_B + aoff,      Bhg + (long long)(n0 + ar) * ldb + k0 + ak);
            CP16(sb + 2 * STG_B + aoff + 16, Bhg + (long long)(n0 + ar) * ldb + k0 + ak + 8);
            CP16(sb + 3 * STG_B + aoff,      Blg + (long long)(n0 + ar) * ldb + k0 + ak);
            CP16(sb + 3 * STG_B + aoff + 16, Blg + (long long)(n0 + ar) * ldb + k0 + ak + 8);
        } else {
            // B global [K,N]: transpose while staging (plain ld/st)
            __nv_bfloat16* Bh = sm + s * (SMEM_STAGE / 2) + 2 * STG_E;
            __nv_bfloat16* Bl = Bh + STG_E;
            const __nv_bfloat16* bh = Bhg + (long long)(k0 + bkk) * ldb + n0 + bnb;
            const __nv_bfloat16* bl = Blg + (long long)(k0 + bkk) * ldb + n0 + bnb;
            uint4 h0 = *(const uint4*)bh, h1 = *(const uint4*)(bh + 8);
            uint4 l0 = *(const uint4*)bl, l1 = *(const uint4*)(bl + 8);
            const __nv_bfloat16* hp0 = (const __nv_bfloat16*)&h0;
            const __nv_bfloat16* hp1 = (const __nv_bfloat16*)&h1;
            const __nv_bfloat16* lp0 = (const __nv_bfloat16*)&l0;
            const __nv_bfloat16* lp1 = (const __nv_bfloat16*)&l1;
#pragma unroll
            for (int j = 0; j < 8; j++) {
                Bh[(bnb + j) * SKP + bkk]     = hp0[j];
                Bh[(bnb + 8 + j) * SKP + bkk] = hp1[j];
                Bl[(bnb + j) * SKP + bkk]     = lp0[j];
                Bl[(bnb + 8 + j) * SKP + bkk] = lp1[j];
            }
        }
        CP_COMMIT();
    };

    issue(0);

    for (int c = 0; c < nchunks; c++) {
        if (c + 1 < nchunks) { issue(c + 1); CP_WAIT(1); }
        else                 { CP_WAIT(0); }
        __syncthreads();

        const uint32_t sb = smb + (c & 1) * SMEM_STAGE;
        const uint32_t AhB = sb, AlB = sb + STG_B;
        const uint32_t BhB = sb + 2 * STG_B, BlB = sb + 3 * STG_B;

#pragma unroll
        for (int ks = 0; ks < 2; ks++) {
            uint32_t aH[4][4], aL[4][4], bHf[4][2], bLf[4][2];
            const int kc = ks * 16 + (lane >> 4) * 8;
#pragma unroll
            for (int m = 0; m < 4; m++) {
                const uint32_t off =
                    (uint32_t)((wy * 64 + m * 16 + (lane & 15)) * SKP + kc) * 2u;
                LDSM_X4(aH[m], AhB + off);
                LDSM_X4(aL[m], AlB + off);
            }
            const int kcb = ks * 16 + ((lane >> 3) & 1) * 8;
#pragma unroll
            for (int n = 0; n < 4; n++) {
                const uint32_t off =
                    (uint32_t)((wx * 32 + n * 8 + (lane & 7)) * SKP + kcb) * 2u;
                LDSM_X2(bHf[n], BhB + off);
                LDSM_X2(bLf[n], BlB + off);
            }
#pragma unroll
            for (int m = 0; m < 4; m++)
#pragma unroll
                for (int n = 0; n < 4; n++) {
                    mma_bf16(acc[m][n], aH[m], bHf[n]);
                    mma_bf16(acc[m][n], aH[m], bLf[n]);
                    mma_bf16(acc[m][n], aL[m], bHf[n]);
                }
        }
        __syncthreads();
    }

    // ---- epilogue ----
#pragma unroll
    for (int m = 0; m < 4; m++) {
        const int row = m0 + wy * 64 + m * 16 + (lane >> 2);
#pragma unroll
        for (int n = 0; n < 4; n++) {
            const int col = n0 + wx * 32 + n * 8 + (lane & 3) * 2;
            float2 v0, v1;
            v0.x = acc[m][n][0] * alpha; v0.y = acc[m][n][1] * alpha;
            v1.x = acc[m][n][2] * alpha; v1.y = acc[m][n][3] * alpha;
            if (outHL) {
                uint32_t h0, l0, h1, l1;
                split2(v0.x, v0.y, h0, l0);
                split2(v1.x, v1.y, h1, l1);
                long long p0 = cOff + (long long)row * ldc + col;
                long long p1 = cOff + (long long)(row + 8) * ldc + col;
                *(uint32_t*)(g_oh + p0) = h0;  *(uint32_t*)(g_ol + p0) = l0;
                *(uint32_t*)(g_oh + p1) = h1;  *(uint32_t*)(g_ol + p1) = l1;
            } else {
                if (bias) {
                    float2 bb = *(const float2*)(bias + col);
                    v0.x += bb.x; v0.y += bb.y;
                    v1.x += bb.x; v1.y += bb.y;
                }
                *(float2*)(C + cOff + (long long)row * ldc + col)       = v0;
                *(float2*)(C + cOff + (long long)(row + 8) * ldc + col) = v1;
            }
        }
    }
}

// ---------------------------------------------------------------------------
// Prep: split qkv -> RMSNorm(q,k) + RoPE -> bf16 hi/lo q,k,v in [B,H,L,D]
// ---------------------------------------------------------------------------
__global__ __launch_bounds__(256) void prep_kernel(
    const float* __restrict__ qkv, const float* __restrict__ pe,
    const float* __restrict__ qsc, const float* __restrict__ ksc)
{
    const int warp = (blockIdx.x * blockDim.x + threadIdx.x) >> 5;
    const int lane = threadIdx.x & 31;
    const int b = warp >> 15;
    const int rem = warp & 32767;
    const int h = rem >> 11;
    const int l = rem & 2047;

    const long long src = ((long long)(b * LL + l)) * E3 + h * DD + lane * 4;
    float4 qv = *(const float4*)(qkv + src);
    float4 kv = *(const float4*)(qkv + src + DIMM);
    float4 vv = *(const float4*)(qkv + src + 2 * DIMM);

    float sq = qv.x * qv.x + qv.y * qv.y + qv.z * qv.z + qv.w * qv.w;
#pragma unroll
    for (int o = 16; o; o >>= 1) sq += __shfl_xor_sync(0xffffffffu, sq, o);
    float rq = rsqrtf(sq * (1.0f / 128.0f) + 1e-6f);
    float4 qs4 = *(const float4*)(qsc + lane * 4);
    qv.x *= rq * qs4.x; qv.y *= rq * qs4.y; qv.z *= rq * qs4.z; qv.w *= rq * qs4.w;

    float sk = kv.x * kv.x + kv.y * kv.y + kv.z * kv.z + kv.w * kv.w;
#pragma unroll
    for (int o = 16; o; o >>= 1) sk += __shfl_xor_sync(0xffffffffu, sk, o);
    float rk = rsqrtf(sk * (1.0f / 128.0f) + 1e-6f);
    float4 ks4 = *(const float4*)(ksc + lane * 4);
    kv.x *= rk * ks4.x; kv.y *= rk * ks4.y; kv.z *= rk * ks4.z; kv.w *= rk * ks4.w;

    const float* peb = pe + (long long)l * 256 + lane * 8;
    float a00 = peb[0], a01 = peb[1], a10 = peb[2], a11 = peb[3];
    float b00 = peb[4], b01 = peb[5], b10 = peb[6], b11 = peb[7];

    float4 qo, ko;
    qo.x = a00 * qv.x + a01 * qv.y;  qo.y = a10 * qv.x + a11 * qv.y;
    qo.z = b00 * qv.z + b01 * qv.w;  qo.w = b10 * qv.z + b11 * qv.w;
    ko.x = a00 * kv.x + a01 * kv.y;  ko.y = a10 * kv.x + a11 * kv.y;
    ko.z = b00 * kv.z + b01 * kv.w;  ko.w = b10 * kv.z + b11 * kv.w;

    const long long dst = (long long)warp * DD + lane * 4;
    uint2 hv, lv;
    split2(qo.x, qo.y, hv.x, lv.x); split2(qo.z, qo.w, hv.y, lv.y);
    *(uint2*)(g_qh + dst) = hv; *(uint2*)(g_ql + dst) = lv;
    split2(ko.x, ko.y, hv.x, lv.x); split2(ko.z, ko.w, hv.y, lv.y);
    *(uint2*)(g_kh + dst) = hv; *(uint2*)(g_kl + dst) = lv;
    split2(vv.x, vv.y, hv.x, lv.x); split2(vv.z, vv.w, hv.y, lv.y);
    *(uint2*)(g_vh + dst) = hv; *(uint2*)(g_vl + dst) = lv;
}

// ---------------------------------------------------------------------------
// Row softmax over last dim (L=2048), fp32 in -> bf16 hi/lo out.
// ---------------------------------------------------------------------------
__global__ __launch_bounds__(256) void softmax_rows(const float* __restrict__ s)
{
    const long long rb = (long long)blockIdx.x * LL;
    const float* p = s + rb;
    const int tid = threadIdx.x;
    const int lane = tid & 31, wid = tid >> 5;
    __shared__ float red[8];

    float2 vals[4];
    float m = NEG_INF_F;
#pragma unroll
    for (int i = 0; i < 4; i++) {
        vals[i] = *(const float2*)(p + tid * 2 + i * 512);
        m = fmaxf(m, fmaxf(vals[i].x, vals[i].y));
    }
#pragma unroll
    for (int o = 16; o; o >>= 1) m = fmaxf(m, __shfl_xor_sync(0xffffffffu, m, o));
    if (lane == 0) red[wid] = m;
    __syncthreads();
    float mm = red[0];
#pragma unroll
    for (int i = 1; i < 8; i++) mm = fmaxf(mm, red[i]);
    __syncthreads();

    float sum = 0.f;
#pragma unroll
    for (int i = 0; i < 4; i++) {
        vals[i].x = __expf(vals[i].x - mm);
        vals[i].y = __expf(vals[i].y - mm);
        sum += vals[i].x + vals[i].y;
    }
#pragma unroll
    for (int o = 16; o; o >>= 1) sum += __shfl_xor_sync(0xffffffffu, sum, o);
    if (lane == 0) red[wid] = sum;
    __syncthreads();
    float total = 0.f;
#pragma unroll
    for (int i = 0; i < 8; i++) total += red[i];
    float inv = 1.0f / total;
#pragma unroll
    for (int i = 0; i < 4; i++) {
        uint32_t h, l;
        split2(vals[i].x * inv, vals[i].y * inv, h, l);
        *(uint32_t*)(g_sh + rb + tid * 2 + i * 512) = h;
        *(uint32_t*)(g_sl + rb + tid * 2 + i * 512) = l;
    }
}

// ---------------------------------------------------------------------------
// Launch
// ---------------------------------------------------------------------------
extern "C" void kernel_launch(void* const* d_in, const int* in_sizes, int n_in,
                              void* d_out, int out_size)
{
    const float* x      = (const float*)d_in[0];
    const float* pe     = (const float*)d_in[1];
    const float* qkv_w  = (const float*)d_in[2];
    const float* q_sc   = (const float*)d_in[3];
    const float* k_sc   = (const float*)d_in[4];
    const float* proj_w = (const float*)d_in[5];
    const float* proj_b = (const float*)d_in[6];
    float* out = (float*)d_out;

    float *qkv, *s;
    __nv_bfloat16 *xh, *xl, *wqh, *wql, *wph, *wpl;
    __nv_bfloat16 *qh, *ql, *kh, *kl, *vh, *vl, *sh, *sl, *oh, *ol;
    cudaGetSymbolAddress((void**)&qkv, g_qkv);
    cudaGetSymbolAddress((void**)&s,   g_s);
    cudaGetSymbolAddress((void**)&xh,  g_xh);  cudaGetSymbolAddress((void**)&xl, g_xl);
    cudaGetSymbolAddress((void**)&wqh, g_wqh); cudaGetSymbolAddress((void**)&wql, g_wql);
    cudaGetSymbolAddress((void**)&wph, g_wph); cudaGetSymbolAddress((void**)&wpl, g_wpl);
    cudaGetSymbolAddress((void**)&qh,  g_qh);  cudaGetSymbolAddress((void**)&ql,  g_ql);
    cudaGetSymbolAddress((void**)&kh,  g_kh);  cudaGetSymbolAddress((void**)&kl,  g_kl);
    cudaGetSymbolAddress((void**)&vh,  g_vh);  cudaGetSymbolAddress((void**)&vl,  g_vl);
    cudaGetSymbolAddress((void**)&sh,  g_sh);  cudaGetSymbolAddress((void**)&sl,  g_sl);
    cudaGetSymbolAddress((void**)&oh,  g_oh);  cudaGetSymbolAddress((void**)&ol,  g_ol);

    cudaFuncSetAttribute(gemm_tc, cudaFuncAttributeMaxDynamicSharedMemorySize, SMEM_TOTAL);

    const float attn_scale = 0.08838834764831845f;  // 1/sqrt(128)

    // 0) Pre-split fp32 inputs into bf16 hi/lo
    convert_hl<<<(MROWS * DIMM / 4 + 255) / 256, 256>>>(x, xh, xl, MROWS * DIMM / 4);
    convert_hl<<<(E3 * DIMM / 4 + 255) / 256, 256>>>(qkv_w, wqh, wql, E3 * DIMM / 4);
    convert_hl<<<(DIMM * DIMM / 4 + 255) / 256, 256>>>(proj_w, wph, wpl, DIMM * DIMM / 4);

    // 1) QKV: [4096,2048] @ [6144,2048]^T -> fp32 [4096,6144]
    gemm_tc<<<dim3(E3 / BN, MROWS / BM, 1), 256, SMEM_TOTAL>>>(
        xh, xl, wqh, wql, qkv, nullptr, DIMM, DIMM, DIMM, E3, 1.0f, 0, 0, 0, 0, 0);

    // 2) RMSNorm + RoPE -> bf16 hi/lo q,k,v
    prep_kernel<<<(BH * LL) / 8, 256>>>(qkv, pe, q_sc, k_sc);

    // 3) Scores: Q @ K^T * scale -> fp32 S
    gemm_tc<<<dim3(LL / BN, LL / BM, BH), 256, SMEM_TOTAL>>>(
        qh, ql, kh, kl, s, nullptr, DD, DD, DD, LL, attn_scale,
        (long long)LL * DD, (long long)LL * DD, (long long)LL * LL, 0, 0);

    // 4) Softmax -> bf16 hi/lo P
    softmax_rows<<<BH * LL, 256>>>(s);

    // 5) P @ V -> bf16 hi/lo o2 [B,L,H*D]  (V is [K=L,N=D]: transB)
    gemm_tc<<<dim3(1, LL / BM, BH), 256, SMEM_TOTAL>>>(
        sh, sl, vh, vl, nullptr, nullptr, LL, LL, DD, DIMM, 1.0f,
        (long long)LL * LL, (long long)LL * DD, 0, 1, 1);

    // 6) Proj + bias -> fp32 out
    gemm_tc<<<dim3(DIMM / BN, MROWS / BM, 1), 256, SMEM_TOTAL>>>(
        oh, ol, wph, wpl, out, proj_b, DIMM, DIMM, DIMM, DIMM, 1.0f, 0, 0, 0, 0, 0);
}

// round 6
// speedup vs baseline: 2.6758x; 1.2213x over previous
#include <cuda_runtime.h>
#include <cuda_bf16.h>
#include <cstdint>
#include <cstddef>

#define BB   2
#define LL   2048
#define DIMM 2048
#define HH   16
#define DD   128
#define E3   6144
#define MROWS (BB*LL)
#define BH   (BB*HH)

#define NEG_INF_F (__int_as_float(0xff800000))

// ---- GEMM tiling (QKV / proj) ----
#define BM 128
#define BN 128
#define SKP 40
#define STG_E (128 * SKP)
#define STG_B (STG_E * 2)
#define SMEM_STAGE (4 * STG_B)
#define SMEM_TOTAL (2 * SMEM_STAGE)

// ---- flash tiling ----
#define FSKP 136                        // row stride elems (272 B)
#define QBYTES (128 * FSKP * 2)         // 34816
#define KVB    (64 * FSKP * 2)          // 17408
#define SM_Q   0
#define SM_S0  (2 * QBYTES)             // 69632
#define FSTAGE (4 * KVB)                // 69632
#define FSMEM  (SM_S0 + 2 * FSTAGE)     // 208896

// ---------------------------------------------------------------------------
// Scratch
// ---------------------------------------------------------------------------
__device__ float g_qkv[(size_t)MROWS * E3];
__device__ __nv_bfloat16 g_xh[(size_t)MROWS * DIMM], g_xl[(size_t)MROWS * DIMM];
__device__ __nv_bfloat16 g_wqh[(size_t)E3 * DIMM],  g_wql[(size_t)E3 * DIMM];
__device__ __nv_bfloat16 g_wph[(size_t)DIMM * DIMM], g_wpl[(size_t)DIMM * DIMM];
__device__ __nv_bfloat16 g_qh[(size_t)BH * LL * DD], g_ql[(size_t)BH * LL * DD];
__device__ __nv_bfloat16 g_kh[(size_t)BH * LL * DD], g_kl[(size_t)BH * LL * DD];
__device__ __nv_bfloat16 g_vh[(size_t)BH * LL * DD], g_vl[(size_t)BH * LL * DD];
__device__ __nv_bfloat16 g_oh[(size_t)MROWS * DIMM], g_ol[(size_t)MROWS * DIMM];

// ---------------------------------------------------------------------------
// PTX helpers
// ---------------------------------------------------------------------------
__device__ __forceinline__ uint32_t smem_u32(const void* p) {
    uint32_t a;
    asm("{ .reg .u64 t; cvta.to.shared.u64 t, %1; cvt.u32.u64 %0, t; }" : "=r"(a) : "l"(p));
    return a;
}

#define CP16(dst, src) \
    asm volatile("cp.async.cg.shared.global [%0], [%1], 16;" :: "r"(dst), "l"(src))
#define CP_COMMIT() asm volatile("cp.async.commit_group;" ::: "memory")
#define CP_WAIT(n)  asm volatile("cp.async.wait_group %0;" :: "n"(n) : "memory")

#define LDSM_X4(r, addr) \
    asm volatile("ldmatrix.sync.aligned.m8n8.x4.shared.b16 {%0,%1,%2,%3}, [%4];" \
        : "=r"((r)[0]), "=r"((r)[1]), "=r"((r)[2]), "=r"((r)[3]) : "r"(addr))
#define LDSM_X2(r, addr) \
    asm volatile("ldmatrix.sync.aligned.m8n8.x2.shared.b16 {%0,%1}, [%2];" \
        : "=r"((r)[0]), "=r"((r)[1]) : "r"(addr))
#define LDSM_X4T(r, addr) \
    asm volatile("ldmatrix.sync.aligned.m8n8.x4.trans.shared.b16 {%0,%1,%2,%3}, [%4];" \
        : "=r"((r)[0]), "=r"((r)[1]), "=r"((r)[2]), "=r"((r)[3]) : "r"(addr))

__device__ __forceinline__ void mma_bf16(float* d, const uint32_t* a, const uint32_t* b) {
    asm volatile(
        "mma.sync.aligned.m16n8k16.row.col.f32.bf16.bf16.f32 "
        "{%0,%1,%2,%3}, {%4,%5,%6,%7}, {%8,%9}, {%0,%1,%2,%3};"
        : "+f"(d[0]), "+f"(d[1]), "+f"(d[2]), "+f"(d[3])
        : "r"(a[0]), "r"(a[1]), "r"(a[2]), "r"(a[3]), "r"(b[0]), "r"(b[1]));
}

__device__ __forceinline__ void split2(float x, float y, uint32_t& hi, uint32_t& lo) {
    __nv_bfloat162 h = __floats2bfloat162_rn(x, y);
    __nv_bfloat162 l = __floats2bfloat162_rn(x - __bfloat162float(h.x),
                                             y - __bfloat162float(h.y));
    hi = *(uint32_t*)&h;
    lo = *(uint32_t*)&l;
}

// ---------------------------------------------------------------------------
// Elementwise fp32 -> bf16 hi/lo converter
// ---------------------------------------------------------------------------
__global__ __launch_bounds__(256) void convert_hl(
    const float* __restrict__ src, __nv_bfloat16* __restrict__ h,
    __nv_bfloat16* __restrict__ l, int n4)
{
    int i = blockIdx.x * blockDim.x + threadIdx.x;
    if (i >= n4) return;
    float4 f = *(const float4*)(src + i * 4);
    uint2 hv, lv;
    split2(f.x, f.y, hv.x, lv.x);
    split2(f.z, f.w, hv.y, lv.y);
    *(uint2*)(h + i * 4) = hv;
    *(uint2*)(l + i * 4) = lv;
}

// ---------------------------------------------------------------------------
// Tensor-core GEMM on pre-split hi/lo inputs (NT): C = A @ B^T (+bias)
// ---------------------------------------------------------------------------
__global__ __launch_bounds__(256) void gemm_tc(
    const __nv_bfloat16* __restrict__ Ahg, const __nv_bfloat16* __restrict__ Alg,
    const __nv_bfloat16* __restrict__ Bhg, const __nv_bfloat16* __restrict__ Blg,
    float* __restrict__ C, const float* __restrict__ bias,
    int K, int lda, int ldb, int ldc)
{
    extern __shared__ __nv_bfloat16 sm[];
    const uint32_t smb = smem_u32(sm);
    const int tid  = threadIdx.x;
    const int lane = tid & 31;
    const int wrp  = tid >> 5;
    const int wy   = wrp >> 2;
    const int wx   = wrp & 3;

    const int m0 = blockIdx.y * BM;
    const int n0 = blockIdx.x * BN;

    float acc[4][4][4];
#pragma unroll
    for (int m = 0; m < 4; m++)
#pragma unroll
        for (int n = 0; n < 4; n++)
#pragma unroll
            for (int i = 0; i < 4; i++) acc[m][n][i] = 0.f;

    const int nchunks = K >> 5;
    const int ar = tid >> 1;
    const int ak = (tid & 1) * 16;

    auto issue = [&](int c) {
        const int s = c & 1;
        const int k0 = c << 5;
        const uint32_t sb = smb + s * SMEM_STAGE;
        const uint32_t aoff = (uint32_t)(ar * SKP + ak) * 2u;
        CP16(sb + aoff,              Ahg + (long long)(m0 + ar) * lda + k0 + ak);
        CP16(sb + aoff + 16,         Ahg + (long long)(m0 + ar) * lda + k0 + ak + 8);
        CP16(sb + STG_B + aoff,      Alg + (long long)(m0 + ar) * lda + k0 + ak);
        CP16(sb + STG_B + aoff + 16, Alg + (long long)(m0 + ar) * lda + k0 + ak + 8);
        CP16(sb + 2 * STG_B + aoff,      Bhg + (long long)(n0 + ar) * ldb + k0 + ak);
        CP16(sb + 2 * STG_B + aoff + 16, Bhg + (long long)(n0 + ar) * ldb + k0 + ak + 8);
        CP16(sb + 3 * STG_B + aoff,      Blg + (long long)(n0 + ar) * ldb + k0 + ak);
        CP16(sb + 3 * STG_B + aoff + 16, Blg + (long long)(n0 + ar) * ldb + k0 + ak + 8);
        CP_COMMIT();
    };

    issue(0);

    for (int c = 0; c < nchunks; c++) {
        if (c + 1 < nchunks) { issue(c + 1); CP_WAIT(1); }
        else                 { CP_WAIT(0); }
        __syncthreads();

        const uint32_t sb = smb + (c & 1) * SMEM_STAGE;
        const uint32_t AhB = sb, AlB = sb + STG_B;
        const uint32_t BhB = sb + 2 * STG_B, BlB = sb + 3 * STG_B;

#pragma unroll
        for (int ks = 0; ks < 2; ks++) {
            uint32_t aH[4][4], aL[4][4], bHf[4][2], bLf[4][2];
            const int kc = ks * 16 + (lane >> 4) * 8;
#pragma unroll
            for (int m = 0; m < 4; m++) {
                const uint32_t off =
                    (uint32_t)((wy * 64 + m * 16 + (lane & 15)) * SKP + kc) * 2u;
                LDSM_X4(aH[m], AhB + off);
                LDSM_X4(aL[m], AlB + off);
            }
            const int kcb = ks * 16 + ((lane >> 3) & 1) * 8;
#pragma unroll
            for (int n = 0; n < 4; n++) {
                const uint32_t off =
                    (uint32_t)((wx * 32 + n * 8 + (lane & 7)) * SKP + kcb) * 2u;
                LDSM_X2(bHf[n], BhB + off);
                LDSM_X2(bLf[n], BlB + off);
            }
#pragma unroll
            for (int m = 0; m < 4; m++)
#pragma unroll
                for (int n = 0; n < 4; n++) {
                    mma_bf16(acc[m][n], aH[m], bHf[n]);
                    mma_bf16(acc[m][n], aH[m], bLf[n]);
                    mma_bf16(acc[m][n], aL[m], bHf[n]);
                }
        }
        __syncthreads();
    }

#pragma unroll
    for (int m = 0; m < 4; m++) {
        const int row = m0 + wy * 64 + m * 16 + (lane >> 2);
#pragma unroll
        for (int n = 0; n < 4; n++) {
            const int col = n0 + wx * 32 + n * 8 + (lane & 3) * 2;
            float2 v0, v1;
            v0.x = acc[m][n][0]; v0.y = acc[m][n][1];
            v1.x = acc[m][n][2]; v1.y = acc[m][n][3];
            if (bias) {
                float2 bb = *(const float2*)(bias + col);
                v0.x += bb.x; v0.y += bb.y;
                v1.x += bb.x; v1.y += bb.y;
            }
            *(float2*)(C + (long long)row * ldc + col)       = v0;
            *(float2*)(C + (long long)(row + 8) * ldc + col) = v1;
        }
    }
}

// ---------------------------------------------------------------------------
// Fused flash attention: per CTA one (b,h) x 128 q-rows; K/V chunks of 64.
// Inputs pre-scaled q (attn_scale folded in prep). Writes bf16 hi/lo O.
// ---------------------------------------------------------------------------
__global__ __launch_bounds__(256, 1) void flash_attn()
{
    extern __shared__ char smc[];
    const uint32_t smb = smem_u32(smc);
    const int tid = threadIdx.x, lane = tid & 31, w = tid >> 5;
    const int m0 = blockIdx.x * 128;
    const int bh = blockIdx.y;
    const long long hb = (long long)bh * LL * DD;
    const __nv_bfloat16 *qhp = g_qh + hb, *qlp = g_ql + hb;
    const __nv_bfloat16 *khp = g_kh + hb, *klp = g_kl + hb;
    const __nv_bfloat16 *vhp = g_vh + hb, *vlp = g_vl + hb;

    // ---- prologue staging: Q + chunk 0 in one cp.async group ----
#pragma unroll
    for (int i = 0; i < 16; i++) {
        int idx = tid + i * 256;
        int mat = idx >> 11, row = (idx >> 4) & 127, seg = idx & 15;
        const __nv_bfloat16* sp = mat ? qlp : qhp;
        CP16(smb + SM_Q + mat * QBYTES + (uint32_t)row * 272u + seg * 16,
             sp + (long long)(m0 + row) * DD + seg * 8);
    }
    auto stage_kv = [&](int c) {
        const uint32_t base = smb + SM_S0 + (uint32_t)(c & 1) * FSTAGE;
#pragma unroll
        for (int i = 0; i < 16; i++) {
            int idx = tid + i * 256;
            int mat = (idx >> 10) & 3, row = (idx >> 4) & 63, seg = idx & 15;
            const __nv_bfloat16* sp = (mat == 0) ? khp : (mat == 1) ? klp
                                    : (mat == 2) ? vhp : vlp;
            CP16(base + (uint32_t)mat * KVB + (uint32_t)row * 272u + seg * 16,
                 sp + (long long)(c * 64 + row) * DD + seg * 8);
        }
    };
    stage_kv(0);
    CP_COMMIT();

    float Oacc[16][4];
#pragma unroll
    for (int n = 0; n < 16; n++)
#pragma unroll
        for (int i = 0; i < 4; i++) Oacc[n][i] = 0.f;
    float mr0 = -1e30f, mr1 = -1e30f, lr0 = 0.f, lr1 = 0.f;

    uint32_t qfh[8][4], qfl[8][4];

    for (int c = 0; c < 32; c++) {
        if (c + 1 < 32) { stage_kv(c + 1); CP_COMMIT(); CP_WAIT(1); }
        else            { CP_WAIT(0); }
        __syncthreads();

        if (c == 0) {
#pragma unroll
            for (int kd = 0; kd < 8; kd++) {
                const uint32_t off =
                    ((uint32_t)(w * 16 + (lane & 15)) * 136u + kd * 16 + (lane >> 4) * 8) * 2u;
                LDSM_X4(qfh[kd], smb + SM_Q + off);
                LDSM_X4(qfl[kd], smb + SM_Q + QBYTES + off);
            }
        }

        const uint32_t stg = smb + SM_S0 + (uint32_t)(c & 1) * FSTAGE;
        const uint32_t Kh = stg, Kl = stg + KVB, Vh = stg + 2 * KVB, Vl = stg + 3 * KVB;

        // ---- S = Q @ K^T (hi/lo 3-MMA) ----
        float sacc[8][4];
#pragma unroll
        for (int n = 0; n < 8; n++)
#pragma unroll
            for (int i = 0; i < 4; i++) sacc[n][i] = 0.f;

#pragma unroll
        for (int kd = 0; kd < 8; kd++) {
            uint32_t bh8[8][2], bl8[8][2];
            const uint32_t kcb = kd * 16 + ((lane >> 3) & 1) * 8;
#pragma unroll
            for (int nf = 0; nf < 8; nf++) {
                const uint32_t off = ((uint32_t)(nf * 8 + (lane & 7)) * 136u + kcb) * 2u;
                LDSM_X2(bh8[nf], Kh + off);
                LDSM_X2(bl8[nf], Kl + off);
            }
#pragma unroll
            for (int nf = 0; nf < 8; nf++) {
                mma_bf16(sacc[nf], qfh[kd], bh8[nf]);
                mma_bf16(sacc[nf], qfh[kd], bl8[nf]);
                mma_bf16(sacc[nf], qfl[kd], bh8[nf]);
            }
        }

        // ---- online softmax ----
        float cm0 = -1e30f, cm1 = -1e30f;
#pragma unroll
        for (int nf = 0; nf < 8; nf++) {
            cm0 = fmaxf(cm0, fmaxf(sacc[nf][0], sacc[nf][1]));
            cm1 = fmaxf(cm1, fmaxf(sacc[nf][2], sacc[nf][3]));
        }
        cm0 = fmaxf(cm0, __shfl_xor_sync(0xffffffffu, cm0, 1));
        cm0 = fmaxf(cm0, __shfl_xor_sync(0xffffffffu, cm0, 2));
        cm1 = fmaxf(cm1, __shfl_xor_sync(0xffffffffu, cm1, 1));
        cm1 = fmaxf(cm1, __shfl_xor_sync(0xffffffffu, cm1, 2));
        const float mn0 = fmaxf(mr0, cm0), mn1 = fmaxf(mr1, cm1);
        const float a0 = __expf(mr0 - mn0), a1 = __expf(mr1 - mn1);
        mr0 = mn0; mr1 = mn1;

        float s0 = 0.f, s1 = 0.f;
#pragma unroll
        for (int nf = 0; nf < 8; nf++) {
            sacc[nf][0] = __expf(sacc[nf][0] - mn0);
            sacc[nf][1] = __expf(sacc[nf][1] - mn0);
            sacc[nf][2] = __expf(sacc[nf][2] - mn1);
            sacc[nf][3] = __expf(sacc[nf][3] - mn1);
            s0 += sacc[nf][0] + sacc[nf][1];
            s1 += sacc[nf][2] + sacc[nf][3];
        }
        s0 += __shfl_xor_sync(0xffffffffu, s0, 1);
        s0 += __shfl_xor_sync(0xffffffffu, s0, 2);
        s1 += __shfl_xor_sync(0xffffffffu, s1, 1);
        s1 += __shfl_xor_sync(0xffffffffu, s1, 2);
        lr0 = lr0 * a0 + s0;
        lr1 = lr1 * a1 + s1;

#pragma unroll
        for (int n = 0; n < 16; n++) {
            Oacc[n][0] *= a0; Oacc[n][1] *= a0;
            Oacc[n][2] *= a1; Oacc[n][3] *= a1;
        }

        // ---- P (accumulator layout) -> A-fragments, hi/lo ----
        uint32_t ph[4][4], pl[4][4];
#pragma unroll
        for (int kv = 0; kv < 4; kv++) {
            split2(sacc[2 * kv][0],     sacc[2 * kv][1],     ph[kv][0], pl[kv][0]);
            split2(sacc[2 * kv][2],     sacc[2 * kv][3],     ph[kv][1], pl[kv][1]);
            split2(sacc[2 * kv + 1][0], sacc[2 * kv + 1][1], ph[kv][2], pl[kv][2]);
            split2(sacc[2 * kv + 1][2], sacc[2 * kv + 1][3], ph[kv][3], pl[kv][3]);
        }

        // ---- O += P @ V ----
#pragma unroll
        for (int kv = 0; kv < 4; kv++) {
            const uint32_t vrow = (uint32_t)(kv * 16 + (lane & 15));
#pragma unroll
            for (int nfp = 0; nfp < 8; nfp++) {
                const uint32_t voff =
                    (vrow * 136u + (uint32_t)(nfp * 16 + ((lane >> 4) & 1) * 8)) * 2u;
                uint32_t vbh[4], vbl[4];
                LDSM_X4T(vbh, Vh + voff);
                LDSM_X4T(vbl, Vl + voff);
                mma_bf16(Oacc[2 * nfp],     ph[kv], vbh);
                mma_bf16(Oacc[2 * nfp],     ph[kv], vbl);
                mma_bf16(Oacc[2 * nfp],     pl[kv], vbh);
                mma_bf16(Oacc[2 * nfp + 1], ph[kv], vbh + 2);
                mma_bf16(Oacc[2 * nfp + 1], ph[kv], vbl + 2);
                mma_bf16(Oacc[2 * nfp + 1], pl[kv], vbh + 2);
            }
        }
        __syncthreads();
    }

    // ---- epilogue: O / l -> bf16 hi/lo at [B, L, H*D] ----
    const float inv0 = 1.f / lr0, inv1 = 1.f / lr1;
    const int b = bh >> 4, h = bh & 15;
    const int r0 = m0 + w * 16 + (lane >> 2);
    const long long base0 = (long long)(b * LL + r0) * DIMM + h * DD;
    const long long base1 = base0 + 8LL * DIMM;
#pragma unroll
    for (int nf = 0; nf < 16; nf++) {
        const int col = nf * 8 + (lane & 3) * 2;
        uint32_t hh, ll;
        split2(Oacc[nf][0] * inv0, Oacc[nf][1] * inv0, hh, ll);
        *(uint32_t*)(g_oh + base0 + col) = hh;
        *(uint32_t*)(g_ol + base0 + col) = ll;
        split2(Oacc[nf][2] * inv1, Oacc[nf][3] * inv1, hh, ll);
        *(uint32_t*)(g_oh + base1 + col) = hh;
        *(uint32_t*)(g_ol + base1 + col) = ll;
    }
}

// ---------------------------------------------------------------------------
// Prep: split qkv -> RMSNorm(q,k) + RoPE -> bf16 hi/lo q,k,v; q pre-scaled.
// ---------------------------------------------------------------------------
__global__ __launch_bounds__(256) void prep_kernel(
    const float* __restrict__ qkv, const float* __restrict__ pe,
    const float* __restrict__ qsc, const float* __restrict__ ksc)
{
    const int warp = (blockIdx.x * blockDim.x + threadIdx.x) >> 5;
    const int lane = threadIdx.x & 31;
    const int b = warp >> 15;
    const int rem = warp & 32767;
    const int h = rem >> 11;
    const int l = rem & 2047;

    const long long src = ((long long)(b * LL + l)) * E3 + h * DD + lane * 4;
    float4 qv = *(const float4*)(qkv + src);
    float4 kv = *(const float4*)(qkv + src + DIMM);
    float4 vv = *(const float4*)(qkv + src + 2 * DIMM);

    float sq = qv.x * qv.x + qv.y * qv.y + qv.z * qv.z + qv.w * qv.w;
#pragma unroll
    for (int o = 16; o; o >>= 1) sq += __shfl_xor_sync(0xffffffffu, sq, o);
    float rq = rsqrtf(sq * (1.0f / 128.0f) + 1e-6f);
    float4 qs4 = *(const float4*)(qsc + lane * 4);
    qv.x *= rq * qs4.x; qv.y *= rq * qs4.y; qv.z *= rq * qs4.z; qv.w *= rq * qs4.w;

    float sk = kv.x * kv.x + kv.y * kv.y + kv.z * kv.z + kv.w * kv.w;
#pragma unroll
    for (int o = 16; o; o >>= 1) sk += __shfl_xor_sync(0xffffffffu, sk, o);
    float rk = rsqrtf(sk * (1.0f / 128.0f) + 1e-6f);
    float4 ks4 = *(const float4*)(ksc + lane * 4);
    kv.x *= rk * ks4.x; kv.y *= rk * ks4.y; kv.z *= rk * ks4.z; kv.w *= rk * ks4.w;

    const float* peb = pe + (long long)l * 256 + lane * 8;
    float a00 = peb[0], a01 = peb[1], a10 = peb[2], a11 = peb[3];
    float b00 = peb[4], b01 = peb[5], b10 = peb[6], b11 = peb[7];

    const float asc = 0.08838834764831845f;  // 1/sqrt(128), folded into q
    float4 qo, ko;
    qo.x = (a00 * qv.x + a01 * qv.y) * asc;  qo.y = (a10 * qv.x + a11 * qv.y) * asc;
    qo.z = (b00 * qv.z + b01 * qv.w) * asc;  qo.w = (b10 * qv.z + b11 * qv.w) * asc;
    ko.x = a00 * kv.x + a01 * kv.y;  ko.y = a10 * kv.x + a11 * kv.y;
    ko.z = b00 * kv.z + b01 * kv.w;  ko.w = b10 * kv.z + b11 * kv.w;

    const long long dst = (long long)warp * DD + lane * 4;
    uint2 hv, lv;
    split2(qo.x, qo.y, hv.x, lv.x); split2(qo.z, qo.w, hv.y, lv.y);
    *(uint2*)(g_qh + dst) = hv; *(uint2*)(g_ql + dst) = lv;
    split2(ko.x, ko.y, hv.x, lv.x); split2(ko.z, ko.w, hv.y, lv.y);
    *(uint2*)(g_kh + dst) = hv; *(uint2*)(g_kl + dst) = lv;
    split2(vv.x, vv.y, hv.x, lv.x); split2(vv.z, vv.w, hv.y, lv.y);
    *(uint2*)(g_vh + dst) = hv; *(uint2*)(g_vl + dst) = lv;
}

// ---------------------------------------------------------------------------
// Launch
// ---------------------------------------------------------------------------
extern "C" void kernel_launch(void* const* d_in, const int* in_sizes, int n_in,
                              void* d_out, int out_size)
{
    const float* x      = (const float*)d_in[0];
    const float* pe     = (const float*)d_in[1];
    const float* qkv_w  = (const float*)d_in[2];
    const float* q_sc   = (const float*)d_in[3];
    const float* k_sc   = (const float*)d_in[4];
    const float* proj_w = (const float*)d_in[5];
    const float* proj_b = (const float*)d_in[6];
    float* out = (float*)d_out;

    float *qkv;
    __nv_bfloat16 *xh, *xl, *wqh, *wql, *wph, *wpl, *oh, *ol;
    cudaGetSymbolAddress((void**)&qkv, g_qkv);
    cudaGetSymbolAddress((void**)&xh,  g_xh);  cudaGetSymbolAddress((void**)&xl, g_xl);
    cudaGetSymbolAddress((void**)&wqh, g_wqh); cudaGetSymbolAddress((void**)&wql, g_wql);
    cudaGetSymbolAddress((void**)&wph, g_wph); cudaGetSymbolAddress((void**)&wpl, g_wpl);
    cudaGetSymbolAddress((void**)&oh,  g_oh);  cudaGetSymbolAddress((void**)&ol,  g_ol);

    cudaFuncSetAttribute(gemm_tc, cudaFuncAttributeMaxDynamicSharedMemorySize, SMEM_TOTAL);
    cudaFuncSetAttribute(flash_attn, cudaFuncAttributeMaxDynamicSharedMemorySize, FSMEM);

    // 0) Pre-split fp32 inputs
    convert_hl<<<(MROWS * DIMM / 4 + 255) / 256, 256>>>(x, xh, xl, MROWS * DIMM / 4);
    convert_hl<<<(E3 * DIMM / 4 + 255) / 256, 256>>>(qkv_w, wqh, wql, E3 * DIMM / 4);
    convert_hl<<<(DIMM * DIMM / 4 + 255) / 256, 256>>>(proj_w, wph, wpl, DIMM * DIMM / 4);

    // 1) QKV projection
    gemm_tc<<<dim3(E3 / BN, MROWS / BM, 1), 256, SMEM_TOTAL>>>(
        xh, xl, wqh, wql, qkv, nullptr, DIMM, DIMM, DIMM, E3);

    // 2) RMSNorm + RoPE (+attn scale) -> hi/lo q,k,v
    prep_kernel<<<(BH * LL) / 8, 256>>>(qkv, pe, q_sc, k_sc);

    // 3) Fused attention -> hi/lo o2 [B,L,H*D]
    flash_attn<<<dim3(LL / 128, BH, 1), 256, FSMEM>>>();

    // 4) Output projection + bias
    gemm_tc<<<dim3(DIMM / BN, MROWS / BM, 1), 256, SMEM_TOTAL>>>(
        oh, ol, wph, wpl, out, proj_b, DIMM, DIMM, DIMM, DIMM);
}